// round 13
// baseline (speedup 1.0000x reference)
#include <cuda_runtime.h>
#include <cstdint>

#define N_NODES 500000
#define N_EDGES 16000000
#define BIT_WORDS 15625            // 500000 / 32 exactly
#define BIT_BYTES (BIT_WORDS * 4)  // 62500

#define NBLOCKS  444               // 148 SMs x 3 CTAs (smem-capped occupancy)
#define NTHREADS 256
#define TOTAL_THREADS (NBLOCKS * NTHREADS)   // 113664, multiple of 32

// Per-node gain: relu(v[n]) * type_params[type[n]].  2 MB, L2-resident.
__device__ float    g_gain[N_NODES];
// 1 bit per node: g_gain[n] != 0.
__device__ unsigned g_bits[BIT_WORDS];

// Generation-based grid barrier state (count returns to 0 after each use;
// gen increases monotonically across uses and graph replays).
__device__ unsigned g_bar_count;
__device__ unsigned g_bar_gen;

// ---------------------------------------------------------------------------
// Software grid barrier. Safe because all NBLOCKS CTAs are co-resident by
// construction (444 = 148 x 3; 62.5KB smem -> exactly 3 CTAs/SM).
// ---------------------------------------------------------------------------
__device__ __forceinline__ void grid_barrier()
{
    __threadfence();                 // publish this thread's prior writes/REDs
    __syncthreads();
    if (threadIdx.x == 0) {
        volatile unsigned* vgen = &g_bar_gen;
        unsigned gen = *vgen;
        __threadfence();             // order gen read before the arrive
        unsigned ticket = atomicAdd(&g_bar_count, 1);
        if (ticket == NBLOCKS - 1) {
            g_bar_count = 0;
            __threadfence();
            atomicAdd(&g_bar_gen, 1);
        } else {
            while (*vgen == gen) { __nanosleep(64); }
        }
    }
    __syncthreads();
}

// ---------------------------------------------------------------------------
// Hard-predicated gather + scatter (exact R9 form, .cg for coherence since
// g_gain is written in phase 1 of this same launch):
// one ISETP guards both the gather load and the no-return atomic.
// ---------------------------------------------------------------------------
__device__ __forceinline__ void edge_op(int bit, const float* gaddr,
                                        float w, float* oaddr)
{
    asm volatile(
        "{\n\t"
        ".reg .pred p;\n\t"
        ".reg .f32  g, m;\n\t"
        "setp.ne.s32 p, %0, 0;\n\t"
        "mov.f32 g, 0f00000000;\n\t"
        "@p ld.global.cg.f32 g, [%1];\n\t"
        "mul.f32 m, g, %2;\n\t"
        "@p red.global.add.f32 [%3], m;\n\t"
        "}"
        :: "r"(bit), "l"(gaddr), "f"(w), "l"(oaddr) : "memory");
}

// ---------------------------------------------------------------------------
// Fused persistent kernel: node prep -> barrier -> edge scatter -> barrier
// -> finalize.
// ---------------------------------------------------------------------------
__global__ void __launch_bounds__(NTHREADS) fused_all(
    const float* __restrict__ voltage,
    const float* __restrict__ stimulus,
    const int*   __restrict__ ntype,       // int32 (JAX x64 off)
    const int4*  __restrict__ src4,        // edge_index row 0, int32 x4
    const int4*  __restrict__ dst4,        // edge_index row 1, int32 x4
    const float4* __restrict__ w4,
    const float* __restrict__ v_rest,
    const float* __restrict__ tau,
    const float* __restrict__ type_params,
    float*       __restrict__ out)
{
    extern __shared__ unsigned sbits[];
    const int gtid = blockIdx.x * NTHREADS + threadIdx.x;

    // ---------------- Phase 1: node prep ----------------
    // Warp-contiguous grid stride (stride multiple of 32, N_NODES multiple
    // of 32) so each warp iteration covers one aligned 32-node bit word.
    for (int i = gtid; i < N_NODES; i += TOTAL_THREADS) {
        float v = voltage[i];
        float r = fmaxf(v, 0.0f);
        int t = ntype[i];                  // values in [0,64)
        float g = r * __ldg(&type_params[t]);
        g_gain[i] = g;
        out[i] = -v + stimulus[i] + v_rest[i];
        unsigned b = __ballot_sync(0xffffffffu, g != 0.0f);
        if ((threadIdx.x & 31) == 0)
            g_bits[i >> 5] = b;
    }

    grid_barrier();

    // ---------------- Phase 2: edge scatter ----------------
    // Bitmap to SMEM (.cg: written by other SMs this launch).
    for (int j = threadIdx.x; j < BIT_WORDS; j += NTHREADS)
        sbits[j] = __ldcg(&g_bits[j]);
    __syncthreads();

    const int n_groups = N_EDGES / 4;      // 4,000,000
    for (int i = gtid; i < n_groups; i += TOTAL_THREADS) {
        // streamed data: evict-first, don't thrash L2-resident g_gain/out
        int4   s = __ldcs(&src4[i]);
        int4   d = __ldcs(&dst4[i]);
        float4 w = __ldcs(&w4[i]);

        int b0 = (sbits[s.x >> 5] >> (s.x & 31)) & 1;
        int b1 = (sbits[s.y >> 5] >> (s.y & 31)) & 1;
        int b2 = (sbits[s.z >> 5] >> (s.z & 31)) & 1;
        int b3 = (sbits[s.w >> 5] >> (s.w & 31)) & 1;

        edge_op(b0, &g_gain[s.x], w.x, &out[d.x]);
        edge_op(b1, &g_gain[s.y], w.y, &out[d.y]);
        edge_op(b2, &g_gain[s.z], w.z, &out[d.z]);
        edge_op(b3, &g_gain[s.w], w.w, &out[d.w]);
    }

    grid_barrier();                        // includes threadfence (REDs visible)

    // ---------------- Phase 3: finalize ----------------
    // out was updated by REDs at L2 from all SMs -> read via .cg (bypass L1).
    for (int i = gtid; i < N_NODES; i += TOTAL_THREADS) {
        out[i] = __ldcg(&out[i]) / tau[i];
    }
}

// ---------------------------------------------------------------------------
// Launch
//   d_in: 0 voltage, 1 stimulus, 2 neuron_type(i32), 3 edge_index(i32 2xE),
//         4 w, 5 V_i_rest, 6 tau_i, 7 type_params
// ---------------------------------------------------------------------------
extern "C" void kernel_launch(void* const* d_in, const int* in_sizes, int n_in,
                              void* d_out, int out_size)
{
    const float* voltage = (const float*)d_in[0];
    const float* stim    = (const float*)d_in[1];
    const int*   ntype   = (const int*)d_in[2];
    const int*   eidx    = (const int*)d_in[3];
    const float* w       = (const float*)d_in[4];
    const float* vrest   = (const float*)d_in[5];
    const float* tau     = (const float*)d_in[6];
    const float* tparams = (const float*)d_in[7];
    float*       out     = (float*)d_out;

    cudaFuncSetAttribute(fused_all,
                         cudaFuncAttributeMaxDynamicSharedMemorySize,
                         BIT_BYTES);

    const int4*   src4 = (const int4*)(eidx);
    const int4*   dst4 = (const int4*)(eidx + N_EDGES);
    const float4* w4   = (const float4*)w;

    fused_all<<<NBLOCKS, NTHREADS, BIT_BYTES>>>(
        voltage, stim, ntype, src4, dst4, w4, vrest, tau, tparams, out);
}

// round 15
// speedup vs baseline: 1.0885x; 1.0885x over previous
#include <cuda_runtime.h>
#include <cstdint>

#define N_NODES 500000
#define N_EDGES 16000000
#define BIT_WORDS 15625            // 500000 / 32 exactly

// Per-node gain: relu(v[n]) * type_params[type[n]].  2 MB, stays L2-hot.
// ~50% of entries are exactly 0.0f (relu of N(0,1) voltage).
__device__ float    g_gain[N_NODES];
// 1 bit per node: g_gain[n] != 0.  62.5 KB -> L1-resident per SM (no smem!).
__device__ unsigned g_bits[BIT_WORDS];

// ---------------------------------------------------------------------------
// Kernel A: node prep. g_gain, zero-bitmap, out[n] = -v + stim + Vrest
// ---------------------------------------------------------------------------
__global__ void node_prep(const float* __restrict__ voltage,
                          const float* __restrict__ stimulus,
                          const int*   __restrict__ ntype,      // int32 (JAX x64 off)
                          const float* __restrict__ v_rest,
                          const float* __restrict__ type_params,
                          float* __restrict__ out,
                          int n)
{
    int i = blockIdx.x * blockDim.x + threadIdx.x;
    float g = 0.0f;
    if (i < n) {
        float v = voltage[i];
        float r = fmaxf(v, 0.0f);
        int t = ntype[i];                 // values in [0,64)
        g = r * __ldg(&type_params[t]);
        g_gain[i] = g;
        out[i] = -v + stimulus[i] + v_rest[i];
    }
    unsigned b = __ballot_sync(0xffffffffu, g != 0.0f);
    if ((threadIdx.x & 31) == 0 && i < n) {
        g_bits[i >> 5] = b;               // warp base i -> word i/32 (< BIT_WORDS)
    }
}

// ---------------------------------------------------------------------------
// Hard-predicated gather + scatter (the R9 form that measured fastest):
// one ISETP guards both the gather load and the no-return atomic; when
// bit==0 NEITHER issues a memory transaction.
// ---------------------------------------------------------------------------
__device__ __forceinline__ void edge_op(int bit, const float* gaddr,
                                        float w, float* oaddr)
{
    asm volatile(
        "{\n\t"
        ".reg .pred p;\n\t"
        ".reg .f32  g, m;\n\t"
        "setp.ne.s32 p, %0, 0;\n\t"
        "mov.f32 g, 0f00000000;\n\t"
        "@p ld.global.nc.f32 g, [%1];\n\t"
        "mul.f32 m, g, %2;\n\t"
        "@p red.global.add.f32 [%3], m;\n\t"
        "}"
        :: "r"(bit), "l"(gaddr), "f"(w), "l"(oaddr) : "memory");
}

// ---------------------------------------------------------------------------
// Kernel B: persistent edge scatter. Zero-bitmap read through L1 (__ldg on
// the 62.5KB g_bits table -> L1-hit after warmup, no L2 traffic, NO SMEM)
// -> occupancy doubles to 6 CTAs/SM (48 warps) for latency hiding.
// ---------------------------------------------------------------------------
__global__ void __launch_bounds__(256, 6) edge_scatter(
    const int4*   __restrict__ src4,   // edge_index row 0, int32 x4
    const int4*   __restrict__ dst4,   // edge_index row 1, int32 x4
    const float4* __restrict__ w4,
    float*        __restrict__ out,
    int n_groups)                      // N_EDGES / 4
{
    int stride = gridDim.x * blockDim.x;
    for (int i = blockIdx.x * blockDim.x + threadIdx.x; i < n_groups; i += stride) {
        // streamed data: evict-first, don't thrash L2-resident g_gain/out
        int4   s = __ldcs(&src4[i]);
        int4   d = __ldcs(&dst4[i]);
        float4 w = __ldcs(&w4[i]);

        // bit tests through L1 (table fits in L1; read-only -> LDG.E.CONSTANT)
        int b0 = (__ldg(&g_bits[s.x >> 5]) >> (s.x & 31)) & 1;
        int b1 = (__ldg(&g_bits[s.y >> 5]) >> (s.y & 31)) & 1;
        int b2 = (__ldg(&g_bits[s.z >> 5]) >> (s.z & 31)) & 1;
        int b3 = (__ldg(&g_bits[s.w >> 5]) >> (s.w & 31)) & 1;

        edge_op(b0, &g_gain[s.x], w.x, &out[d.x]);
        edge_op(b1, &g_gain[s.y], w.y, &out[d.y]);
        edge_op(b2, &g_gain[s.z], w.z, &out[d.z]);
        edge_op(b3, &g_gain[s.w], w.w, &out[d.w]);
    }
}

// ---------------------------------------------------------------------------
// Kernel C: out[n] = out[n] / tau[n]
// ---------------------------------------------------------------------------
__global__ void finalize(const float* __restrict__ tau,
                         float* __restrict__ out,
                         int n)
{
    int i = blockIdx.x * blockDim.x + threadIdx.x;
    if (i < n) {
        out[i] = out[i] / tau[i];
    }
}

// ---------------------------------------------------------------------------
// Launch
//   d_in: 0 voltage, 1 stimulus, 2 neuron_type(i32), 3 edge_index(i32 2xE),
//         4 w, 5 V_i_rest, 6 tau_i, 7 type_params
// ---------------------------------------------------------------------------
extern "C" void kernel_launch(void* const* d_in, const int* in_sizes, int n_in,
                              void* d_out, int out_size)
{
    const float* voltage = (const float*)d_in[0];
    const float* stim    = (const float*)d_in[1];
    const int*   ntype   = (const int*)d_in[2];
    const int*   eidx    = (const int*)d_in[3];
    const float* w       = (const float*)d_in[4];
    const float* vrest   = (const float*)d_in[5];
    const float* tau     = (const float*)d_in[6];
    const float* tparams = (const float*)d_in[7];
    float*       out     = (float*)d_out;

    const int n_nodes = N_NODES;
    const int n_edges = N_EDGES;

    // Kernel A
    {
        int threads = 256;
        int blocks = (n_nodes + threads - 1) / threads;
        node_prep<<<blocks, threads>>>(voltage, stim, ntype, vrest, tparams,
                                       out, n_nodes);
    }

    // Kernel B: persistent, 6 blocks/SM (no smem), 256 thr/block
    {
        const int4*   src4 = (const int4*)(eidx);
        const int4*   dst4 = (const int4*)(eidx + n_edges);
        const float4* w4   = (const float4*)w;
        int n_groups = n_edges / 4;           // 4,000,000 (exact)
        int threads = 256;
        int blocks = 148 * 6;                 // persistent wave, 48 warps/SM
        edge_scatter<<<blocks, threads>>>(src4, dst4, w4, out, n_groups);
    }

    // Kernel C
    {
        int threads = 256;
        int blocks = (n_nodes + threads - 1) / threads;
        finalize<<<blocks, threads>>>(tau, out, n_nodes);
    }
}